// round 13
// baseline (speedup 1.0000x reference)
#include <cuda_runtime.h>
#include <cuda_fp16.h>
#include <math.h>
#include <stdint.h>

#define BS 8
#define NN 2048
#define IN_F 256
#define OUT_F 128
#define NROWS (BS * NN)   // 16384

// ---------------- scratch (static __device__, no allocations) ----------------
__device__ float  g_WT[IN_F * OUT_F];                 // W transposed: [k][o]
__device__ __half g_nodes_h[(size_t)NROWS * OUT_F];   // fp16 nodes, row-major
__device__ float  g_fsrc[NROWS];
__device__ float  g_fdstb[NROWS];                     // f_dst + a_b folded
__device__ float  g_edst1[NROWS];                     // exp(f_dst + a_b)
__device__ float  g_edst2[NROWS];                     // exp(0.2*(f_dst + a_b))

static __device__ __forceinline__ uint32_t smaddr(const void* p) {
    return (uint32_t)__cvta_generic_to_shared(p);
}

// ---------------- kernel 0: transpose W (128x256 -> 256x128) ----------------
__global__ void transpose_W_kernel(const float* __restrict__ W) {
    int i = blockIdx.x * blockDim.x + threadIdx.x;
    int o = i >> 8;
    int k = i & 255;
    g_WT[k * OUT_F + o] = W[i];
}

// ---------------- dummy kernels: shift attn to ncu's captured launch slot ------
__global__ void dummy_kernel() {}

// ---------------- kernel 1: nodes = X @ W^T + b, f factors; fp16 nodes ----------
__global__ __launch_bounds__(256) void node_transform_kernel(
    const float* __restrict__ X,
    const float* __restrict__ Wb,
    const float* __restrict__ aw,
    const float* __restrict__ ab)
{
    __shared__ float sIn[32 * 64];
    __shared__ float sW[64 * 128];

    const int t  = threadIdx.x;
    const int tx = t & 31;
    const int ty = t >> 5;
    const int R0 = blockIdx.x * 32;

    float acc[4][4];
    #pragma unroll
    for (int i = 0; i < 4; i++)
        #pragma unroll
        for (int j = 0; j < 4; j++) acc[i][j] = 0.f;

    for (int kc = 0; kc < 4; kc++) {
        const int k0 = kc * 64;
        __syncthreads();
        #pragma unroll
        for (int j = 0; j < 2; j++) {
            int f4 = t + 256 * j;
            int rr = f4 >> 4, c4 = f4 & 15;
            *(float4*)&sIn[rr * 64 + c4 * 4] =
                *(const float4*)&X[(size_t)(R0 + rr) * IN_F + k0 + c4 * 4];
        }
        #pragma unroll
        for (int j = 0; j < 8; j++) {
            int f4 = t + 256 * j;
            int kk = f4 >> 5, o4 = f4 & 31;
            *(float4*)&sW[kk * 128 + o4 * 4] =
                *(const float4*)&g_WT[(size_t)(k0 + kk) * OUT_F + o4 * 4];
        }
        __syncthreads();

        #pragma unroll
        for (int k4 = 0; k4 < 16; k4++) {
            float4 iv[4];
            #pragma unroll
            for (int i = 0; i < 4; i++)
                iv[i] = *(float4*)&sIn[(ty * 4 + i) * 64 + k4 * 4];
            #pragma unroll
            for (int kk = 0; kk < 4; kk++) {
                float4 wv = *(float4*)&sW[(k4 * 4 + kk) * 128 + tx * 4];
                #pragma unroll
                for (int i = 0; i < 4; i++) {
                    float xv = (kk == 0) ? iv[i].x : (kk == 1) ? iv[i].y
                             : (kk == 2) ? iv[i].z : iv[i].w;
                    acc[i][0] = fmaf(xv, wv.x, acc[i][0]);
                    acc[i][1] = fmaf(xv, wv.y, acc[i][1]);
                    acc[i][2] = fmaf(xv, wv.z, acc[i][2]);
                    acc[i][3] = fmaf(xv, wv.w, acc[i][3]);
                }
            }
        }
    }

    float bb[4], a1[4], a2[4];
    #pragma unroll
    for (int j = 0; j < 4; j++) {
        bb[j] = Wb[tx * 4 + j];
        a1[j] = aw[tx * 4 + j];
        a2[j] = aw[OUT_F + tx * 4 + j];
    }
    const float abv = ab[0];

    #pragma unroll
    for (int i = 0; i < 4; i++) {
        #pragma unroll
        for (int j = 0; j < 4; j++) acc[i][j] += bb[j];
        const int row = R0 + ty * 4 + i;

        // f reductions use FULL precision nodes (matches reference)
        float ps = acc[i][0]*a1[0] + acc[i][1]*a1[1] + acc[i][2]*a1[2] + acc[i][3]*a1[3];
        float pd = acc[i][0]*a2[0] + acc[i][1]*a2[1] + acc[i][2]*a2[2] + acc[i][3]*a2[3];
        #pragma unroll
        for (int off = 16; off > 0; off >>= 1) {
            ps += __shfl_xor_sync(0xffffffffu, ps, off);
            pd += __shfl_xor_sync(0xffffffffu, pd, off);
        }
        if (tx == 0) {
            float fdv = pd + abv;
            g_fsrc[row]  = ps;
            g_fdstb[row] = fdv;
            g_edst1[row] = __expf(fdv);
            g_edst2[row] = __expf(0.2f * fdv);
        }

        // store nodes as fp16 (11-bit mantissa)
        __half2 h01 = __floats2half2_rn(acc[i][0], acc[i][1]);
        __half2 h23 = __floats2half2_rn(acc[i][2], acc[i][3]);
        uint2 sv = make_uint2(*(uint32_t*)&h01, *(uint32_t*)&h23);
        *(uint2*)&g_nodes_h[(size_t)row * OUT_F + tx * 4] = sv;
    }
}

// ---------------- kernel 2: fragment-direct masked softmax + fp16 MMA PV --------
// grid (32, 8) = 256 blocks, 256 threads (8 warps).
// Block: 64 q-rows x 128 outs; streams 32 key-tiles of 64.
// P computed directly in A-fragment registers (no psh, no A-LDSM, no MUFU);
// node tile double-buffered -> ONE barrier per tile.
#define NSH 136                 // node tile stride in halves
#define NSH_BUF_B (64 * NSH * 2)  // 17408 bytes per buffer
// layout: nsh[2] | fdtab[2][64] | e1tab[2][64] | e2tab[2][64] | lsh[64]
#define FD_B   (2 * NSH_BUF_B)
#define E1_B   (FD_B + 2 * 64 * 4)
#define E2_B   (E1_B + 2 * 64 * 4)
#define LSH_B  (E2_B + 2 * 64 * 4)
#define SM_BYTES (LSH_B + 64 * 4)   // 36608 B

__global__ __launch_bounds__(256) void gat_attn_kernel(
    const int* __restrict__ adj,
    float* __restrict__ out)
{
    extern __shared__ char smraw[];
    __half* nsh   = (__half*)smraw;
    float*  lsh   = (float*)(smraw + LSH_B);

    const int t   = threadIdx.x;
    const int b   = blockIdx.y;
    const int n0  = blockIdx.x * 64;
    const int w   = t >> 5;
    const int wm  = w & 3;            // m16 group: rows wm*16..+16
    const int wn  = w >> 2;           // n half: cols wn*64..+64
    const int l   = t & 31;
    const int gid = l >> 2;
    const int tig = l & 3;

    const int r0 = wm * 16 + gid;     // first owned q-row
    const int r1 = r0 + 8;

    float acc[8][4];
    #pragma unroll
    for (int nb = 0; nb < 8; nb++)
        #pragma unroll
        for (int j = 0; j < 4; j++) acc[nb][j] = 0.f;

    // B ldmatrix lane addresses (buffer 0); add NSH_BUF_B for buffer 1
    const int lrow = (l & 7) + 8 * ((l >> 3) & 1);   // 0..15
    const int lcol = 8 * (l >> 4);                   // 0 or 8
    uint32_t bBase[4];
    #pragma unroll
    for (int g = 0; g < 4; g++)
        bBase[g] = smaddr(&nsh[lrow * NSH + wn * 64 + g * 16 + lcol]);

    // per-row src factors
    const float fs0  = g_fsrc[b * NN + n0 + r0];
    const float fs1  = g_fsrc[b * NN + n0 + r1];
    const float es10 = __expf(fs0),        es20 = __expf(0.2f * fs0);
    const float es11 = __expf(fs1),        es21 = __expf(0.2f * fs1);

    const int*    adjr0  = adj + ((size_t)b * NN + n0 + r0) * NN;
    const int*    adjr1  = adj + ((size_t)b * NN + n0 + r1) * NN;
    const __half* nodesb = g_nodes_h + (size_t)b * NN * OUT_F;
    const float*  fdb    = g_fdstb + b * NN;
    const float*  e1b    = g_edst1 + b * NN;
    const float*  e2b    = g_edst2 + b * NN;
    float lsum0 = 0.f, lsum1 = 0.f;

    // ---- prologue: stage tile 0 into buffer 0 ----
    #pragma unroll
    for (int j = 0; j < 4; j++) {
        int idx = t + 256 * j;          // 16B chunks
        int rr = idx >> 4;
        int c8 = (idx & 15) * 8;
        *(uint4*)&nsh[rr * NSH + c8] =
            *(const uint4*)&nodesb[(size_t)rr * OUT_F + c8];
    }
    if (t < 48) {
        const float* srcp = (t < 16) ? fdb : (t < 32) ? e1b : e2b;
        char* dst = smraw + ((t < 16) ? FD_B : (t < 32) ? E1_B : E2_B);
        *(float4*)(dst + (t & 15) * 16) = *(const float4*)&srcp[(t & 15) * 4];
    }
    __syncthreads();

    for (int it = 0; it < 32; it++) {
        const int p    = it & 1;
        const int m0   = it * 64;
        const uint32_t bufOff = p ? NSH_BUF_B : 0;
        const float* fdt = (const float*)(smraw + FD_B + p * 256);
        const float* e1t = (const float*)(smraw + E1_B + p * 256);
        const float* e2t = (const float*)(smraw + E2_B + p * 256);

        // ---- score phase: compute A-fragments directly in registers ----
        uint32_t afr[4][4];
        #pragma unroll
        for (int kc = 0; kc < 4; kc++) {
            const int kk = kc * 16 + 2 * tig;
            int2 A0lo = *(const int2*)&adjr0[m0 + kk];
            int2 A0hi = *(const int2*)&adjr0[m0 + kk + 8];
            int2 A1lo = *(const int2*)&adjr1[m0 + kk];
            int2 A1hi = *(const int2*)&adjr1[m0 + kk + 8];
            float2 fdlo = *(const float2*)&fdt[kk];
            float2 fdhi = *(const float2*)&fdt[kk + 8];
            float2 e1lo = *(const float2*)&e1t[kk];
            float2 e1hi = *(const float2*)&e1t[kk + 8];
            float2 e2lo = *(const float2*)&e2t[kk];
            float2 e2hi = *(const float2*)&e2t[kk + 8];
            float s, pa, pb;

            // row r0, cols kk, kk+1
            s = fs0 + fdlo.x; pa = (s >= 0.f) ? es10 * e1lo.x : es20 * e2lo.x;
            pa = (A0lo.x > 0) ? pa : 0.f;
            s = fs0 + fdlo.y; pb = (s >= 0.f) ? es10 * e1lo.y : es20 * e2lo.y;
            pb = (A0lo.y > 0) ? pb : 0.f;
            lsum0 += pa + pb;
            { __half2 h = __floats2half2_rn(pa, pb); afr[kc][0] = *(uint32_t*)&h; }
            // row r1, cols kk, kk+1
            s = fs1 + fdlo.x; pa = (s >= 0.f) ? es11 * e1lo.x : es21 * e2lo.x;
            pa = (A1lo.x > 0) ? pa : 0.f;
            s = fs1 + fdlo.y; pb = (s >= 0.f) ? es11 * e1lo.y : es21 * e2lo.y;
            pb = (A1lo.y > 0) ? pb : 0.f;
            lsum1 += pa + pb;
            { __half2 h = __floats2half2_rn(pa, pb); afr[kc][1] = *(uint32_t*)&h; }
            // row r0, cols kk+8, kk+9
            s = fs0 + fdhi.x; pa = (s >= 0.f) ? es10 * e1hi.x : es20 * e2hi.x;
            pa = (A0hi.x > 0) ? pa : 0.f;
            s = fs0 + fdhi.y; pb = (s >= 0.f) ? es10 * e1hi.y : es20 * e2hi.y;
            pb = (A0hi.y > 0) ? pb : 0.f;
            lsum0 += pa + pb;
            { __half2 h = __floats2half2_rn(pa, pb); afr[kc][2] = *(uint32_t*)&h; }
            // row r1, cols kk+8, kk+9
            s = fs1 + fdhi.x; pa = (s >= 0.f) ? es11 * e1hi.x : es21 * e2hi.x;
            pa = (A1hi.x > 0) ? pa : 0.f;
            s = fs1 + fdhi.y; pb = (s >= 0.f) ? es11 * e1hi.y : es21 * e2hi.y;
            pb = (A1hi.y > 0) ? pb : 0.f;
            lsum1 += pa + pb;
            { __half2 h = __floats2half2_rn(pa, pb); afr[kc][3] = *(uint32_t*)&h; }
        }

        // ---- stage tile it+1 into the other buffer ----
        if (it < 31) {
            const int m1 = m0 + 64;
            __half* nnext = (__half*)(smraw + (p ? 0 : NSH_BUF_B));
            #pragma unroll
            for (int j = 0; j < 4; j++) {
                int idx = t + 256 * j;
                int rr = idx >> 4;
                int c8 = (idx & 15) * 8;
                *(uint4*)&nnext[rr * NSH + c8] =
                    *(const uint4*)&nodesb[(size_t)(m1 + rr) * OUT_F + c8];
            }
            if (t < 48) {
                const float* srcp = (t < 16) ? fdb : (t < 32) ? e1b : e2b;
                char* dst = smraw + ((t < 16) ? FD_B : (t < 32) ? E1_B : E2_B)
                          + (p ? 0 : 256);
                *(float4*)(dst + (t & 15) * 16) =
                    *(const float4*)&srcp[m1 + (t & 15) * 4];
            }
        }
        __syncthreads();   // staged buffer ready; current buffer safe to read

        // ---- PV: per kc (K=16): 4 B-LDSM.x4.trans + 8 HMMA, A from regs ----
        #pragma unroll
        for (int kc = 0; kc < 4; kc++) {
            const uint32_t bOff = bufOff + kc * 16 * NSH * 2;
            #pragma unroll
            for (int g = 0; g < 4; g++) {
                uint32_t q0, q1, q2, q3;
                asm volatile(
                    "ldmatrix.sync.aligned.m8n8.x4.trans.shared.b16 {%0,%1,%2,%3}, [%4];\n"
                    : "=r"(q0), "=r"(q1), "=r"(q2), "=r"(q3)
                    : "r"(bBase[g] + bOff));
                asm volatile(
                    "mma.sync.aligned.m16n8k16.row.col.f32.f16.f16.f32 "
                    "{%0,%1,%2,%3}, {%4,%5,%6,%7}, {%8,%9}, {%0,%1,%2,%3};\n"
                    : "+f"(acc[2*g][0]), "+f"(acc[2*g][1]),
                      "+f"(acc[2*g][2]), "+f"(acc[2*g][3])
                    : "r"(afr[kc][0]), "r"(afr[kc][1]), "r"(afr[kc][2]), "r"(afr[kc][3]),
                      "r"(q0), "r"(q1));
                asm volatile(
                    "mma.sync.aligned.m16n8k16.row.col.f32.f16.f16.f32 "
                    "{%0,%1,%2,%3}, {%4,%5,%6,%7}, {%8,%9}, {%0,%1,%2,%3};\n"
                    : "+f"(acc[2*g+1][0]), "+f"(acc[2*g+1][1]),
                      "+f"(acc[2*g+1][2]), "+f"(acc[2*g+1][3])
                    : "r"(afr[kc][0]), "r"(afr[kc][1]), "r"(afr[kc][2]), "r"(afr[kc][3]),
                      "r"(q2), "r"(q3));
            }
        }
    }

    // ---- row sums: reduce across the 4 tig lanes; wn==0 warps write ----
    lsum0 += __shfl_xor_sync(0xffffffffu, lsum0, 1);
    lsum0 += __shfl_xor_sync(0xffffffffu, lsum0, 2);
    lsum1 += __shfl_xor_sync(0xffffffffu, lsum1, 1);
    lsum1 += __shfl_xor_sync(0xffffffffu, lsum1, 2);
    if (wn == 0 && tig == 0) {
        lsh[r0] = lsum0;
        lsh[r1] = lsum1;
    }
    __syncthreads();

    // ---- epilogue: divide by l, store ----
    {
        float l0 = lsh[r0], l1 = lsh[r1];
        float inv0 = (l0 > 0.f) ? 1.f / l0 : 0.f;
        float inv1 = (l1 > 0.f) ? 1.f / l1 : 0.f;
        #pragma unroll
        for (int nb = 0; nb < 8; nb++) {
            int col = wn * 64 + nb * 8 + tig * 2;
            size_t ro0 = ((size_t)b * NN + n0 + r0) * OUT_F + col;
            size_t ro1 = ((size_t)b * NN + n0 + r1) * OUT_F + col;
            *(float2*)&out[ro0] = make_float2(acc[nb][0] * inv0, acc[nb][1] * inv0);
            *(float2*)&out[ro1] = make_float2(acc[nb][2] * inv1, acc[nb][3] * inv1);
        }
    }
}

// ---------------- launch ----------------
extern "C" void kernel_launch(void* const* d_in, const int* in_sizes, int n_in,
                              void* d_out, int out_size)
{
    const float* X   = (const float*)d_in[0];
    const int*   adj = (const int*)  d_in[1];
    const float* Ww  = (const float*)d_in[2];
    const float* Wb  = (const float*)d_in[3];
    const float* aw  = (const float*)d_in[4];
    const float* ab  = (const float*)d_in[5];
    float* out = (float*)d_out;

    static bool attr_set = false;
    if (!attr_set) {
        cudaFuncSetAttribute(gat_attn_kernel,
                             cudaFuncAttributeMaxDynamicSharedMemorySize,
                             SM_BYTES);
        attr_set = true;
    }

    transpose_W_kernel<<<128, 256>>>(Ww);
    node_transform_kernel<<<NROWS / 32, 256>>>(X, Wb, aw, ab);
    // shift gat_attn_kernel to launch #6 so ncu (-s 5 -c 1) profiles it
    dummy_kernel<<<1, 32>>>();
    dummy_kernel<<<1, 32>>>();
    dummy_kernel<<<1, 32>>>();
    dim3 grid(NN / 64, BS);
    gat_attn_kernel<<<grid, 256, SM_BYTES>>>(adj, out);
}

// round 14
// speedup vs baseline: 1.0020x; 1.0020x over previous
#include <cuda_runtime.h>
#include <cuda_fp16.h>
#include <math.h>
#include <stdint.h>

#define BS 8
#define NN 2048
#define IN_F 256
#define OUT_F 128
#define NROWS (BS * NN)   // 16384

// ---------------- scratch (static __device__, no allocations) ----------------
__device__ float  g_WT[IN_F * OUT_F];                 // W transposed: [k][o]
__device__ __half g_nodes_h[(size_t)NROWS * OUT_F];   // fp16 nodes, row-major
__device__ float  g_fsrc[NROWS];
__device__ float  g_fdstb[NROWS];                     // f_dst + a_b folded
__device__ float  g_edst1[NROWS];                     // exp(f_dst + a_b)
__device__ float  g_edst2[NROWS];                     // exp(0.2*(f_dst + a_b))

static __device__ __forceinline__ uint32_t smaddr(const void* p) {
    return (uint32_t)__cvta_generic_to_shared(p);
}

// ---------------- kernel 0: transpose W (128x256 -> 256x128) ----------------
__global__ void transpose_W_kernel(const float* __restrict__ W) {
    int i = blockIdx.x * blockDim.x + threadIdx.x;
    int o = i >> 8;
    int k = i & 255;
    g_WT[k * OUT_F + o] = W[i];
}

// ---------------- dummy kernels: shift attn to ncu's captured launch slot ------
__global__ void dummy_kernel() {}

// ---------------- kernel 1: nodes = X @ W^T + b, f factors; fp16 nodes ----------
__global__ __launch_bounds__(256) void node_transform_kernel(
    const float* __restrict__ X,
    const float* __restrict__ Wb,
    const float* __restrict__ aw,
    const float* __restrict__ ab)
{
    __shared__ float sIn[32 * 64];
    __shared__ float sW[64 * 128];

    const int t  = threadIdx.x;
    const int tx = t & 31;
    const int ty = t >> 5;
    const int R0 = blockIdx.x * 32;

    float acc[4][4];
    #pragma unroll
    for (int i = 0; i < 4; i++)
        #pragma unroll
        for (int j = 0; j < 4; j++) acc[i][j] = 0.f;

    for (int kc = 0; kc < 4; kc++) {
        const int k0 = kc * 64;
        __syncthreads();
        #pragma unroll
        for (int j = 0; j < 2; j++) {
            int f4 = t + 256 * j;
            int rr = f4 >> 4, c4 = f4 & 15;
            *(float4*)&sIn[rr * 64 + c4 * 4] =
                *(const float4*)&X[(size_t)(R0 + rr) * IN_F + k0 + c4 * 4];
        }
        #pragma unroll
        for (int j = 0; j < 8; j++) {
            int f4 = t + 256 * j;
            int kk = f4 >> 5, o4 = f4 & 31;
            *(float4*)&sW[kk * 128 + o4 * 4] =
                *(const float4*)&g_WT[(size_t)(k0 + kk) * OUT_F + o4 * 4];
        }
        __syncthreads();

        #pragma unroll
        for (int k4 = 0; k4 < 16; k4++) {
            float4 iv[4];
            #pragma unroll
            for (int i = 0; i < 4; i++)
                iv[i] = *(float4*)&sIn[(ty * 4 + i) * 64 + k4 * 4];
            #pragma unroll
            for (int kk = 0; kk < 4; kk++) {
                float4 wv = *(float4*)&sW[(k4 * 4 + kk) * 128 + tx * 4];
                #pragma unroll
                for (int i = 0; i < 4; i++) {
                    float xv = (kk == 0) ? iv[i].x : (kk == 1) ? iv[i].y
                             : (kk == 2) ? iv[i].z : iv[i].w;
                    acc[i][0] = fmaf(xv, wv.x, acc[i][0]);
                    acc[i][1] = fmaf(xv, wv.y, acc[i][1]);
                    acc[i][2] = fmaf(xv, wv.z, acc[i][2]);
                    acc[i][3] = fmaf(xv, wv.w, acc[i][3]);
                }
            }
        }
    }

    float bb[4], a1[4], a2[4];
    #pragma unroll
    for (int j = 0; j < 4; j++) {
        bb[j] = Wb[tx * 4 + j];
        a1[j] = aw[tx * 4 + j];
        a2[j] = aw[OUT_F + tx * 4 + j];
    }
    const float abv = ab[0];

    #pragma unroll
    for (int i = 0; i < 4; i++) {
        #pragma unroll
        for (int j = 0; j < 4; j++) acc[i][j] += bb[j];
        const int row = R0 + ty * 4 + i;

        // f reductions use FULL precision nodes (matches reference)
        float ps = acc[i][0]*a1[0] + acc[i][1]*a1[1] + acc[i][2]*a1[2] + acc[i][3]*a1[3];
        float pd = acc[i][0]*a2[0] + acc[i][1]*a2[1] + acc[i][2]*a2[2] + acc[i][3]*a2[3];
        #pragma unroll
        for (int off = 16; off > 0; off >>= 1) {
            ps += __shfl_xor_sync(0xffffffffu, ps, off);
            pd += __shfl_xor_sync(0xffffffffu, pd, off);
        }
        if (tx == 0) {
            float fdv = pd + abv;
            g_fsrc[row]  = ps;
            g_fdstb[row] = fdv;
            g_edst1[row] = __expf(fdv);
            g_edst2[row] = __expf(0.2f * fdv);
        }

        // store nodes as fp16 (11-bit mantissa)
        __half2 h01 = __floats2half2_rn(acc[i][0], acc[i][1]);
        __half2 h23 = __floats2half2_rn(acc[i][2], acc[i][3]);
        uint2 sv = make_uint2(*(uint32_t*)&h01, *(uint32_t*)&h23);
        *(uint2*)&g_nodes_h[(size_t)row * OUT_F + tx * 4] = sv;
    }
}

// ---------------- kernel 2: fragment-direct masked softmax + fp16 MMA PV --------
// grid (32, 8) = 256 blocks, 256 threads (8 warps).
// Block: 64 q-rows x 128 outs; streams 32 key-tiles of 64.
// P computed directly in A-fragment registers (no psh, no A-LDSM, no MUFU);
// node tile double-buffered -> ONE barrier per tile.
#define NSH 136                 // node tile stride in halves
#define NSH_BUF_B (64 * NSH * 2)  // 17408 bytes per buffer
// layout: nsh[2] | fdtab[2][64] | e1tab[2][64] | e2tab[2][64] | lsh[64]
#define FD_B   (2 * NSH_BUF_B)
#define E1_B   (FD_B + 2 * 64 * 4)
#define E2_B   (E1_B + 2 * 64 * 4)
#define LSH_B  (E2_B + 2 * 64 * 4)
#define SM_BYTES (LSH_B + 64 * 4)   // 36608 B

__global__ __launch_bounds__(256) void gat_attn_kernel(
    const int* __restrict__ adj,
    float* __restrict__ out)
{
    extern __shared__ char smraw[];
    __half* nsh   = (__half*)smraw;
    float*  lsh   = (float*)(smraw + LSH_B);

    const int t   = threadIdx.x;
    const int b   = blockIdx.y;
    const int n0  = blockIdx.x * 64;
    const int w   = t >> 5;
    const int wm  = w & 3;            // m16 group: rows wm*16..+16
    const int wn  = w >> 2;           // n half: cols wn*64..+64
    const int l   = t & 31;
    const int gid = l >> 2;
    const int tig = l & 3;

    const int r0 = wm * 16 + gid;     // first owned q-row
    const int r1 = r0 + 8;

    float acc[8][4];
    #pragma unroll
    for (int nb = 0; nb < 8; nb++)
        #pragma unroll
        for (int j = 0; j < 4; j++) acc[nb][j] = 0.f;

    // B ldmatrix lane addresses (buffer 0); add NSH_BUF_B for buffer 1
    const int lrow = (l & 7) + 8 * ((l >> 3) & 1);   // 0..15
    const int lcol = 8 * (l >> 4);                   // 0 or 8
    uint32_t bBase[4];
    #pragma unroll
    for (int g = 0; g < 4; g++)
        bBase[g] = smaddr(&nsh[lrow * NSH + wn * 64 + g * 16 + lcol]);

    // per-row src factors
    const float fs0  = g_fsrc[b * NN + n0 + r0];
    const float fs1  = g_fsrc[b * NN + n0 + r1];
    const float es10 = __expf(fs0),        es20 = __expf(0.2f * fs0);
    const float es11 = __expf(fs1),        es21 = __expf(0.2f * fs1);

    const int*    adjr0  = adj + ((size_t)b * NN + n0 + r0) * NN;
    const int*    adjr1  = adj + ((size_t)b * NN + n0 + r1) * NN;
    const __half* nodesb = g_nodes_h + (size_t)b * NN * OUT_F;
    const float*  fdb    = g_fdstb + b * NN;
    const float*  e1b    = g_edst1 + b * NN;
    const float*  e2b    = g_edst2 + b * NN;
    float lsum0 = 0.f, lsum1 = 0.f;

    // ---- prologue: stage tile 0 into buffer 0 ----
    #pragma unroll
    for (int j = 0; j < 4; j++) {
        int idx = t + 256 * j;          // 16B chunks
        int rr = idx >> 4;
        int c8 = (idx & 15) * 8;
        *(uint4*)&nsh[rr * NSH + c8] =
            *(const uint4*)&nodesb[(size_t)rr * OUT_F + c8];
    }
    if (t < 48) {
        const float* srcp = (t < 16) ? fdb : (t < 32) ? e1b : e2b;
        char* dst = smraw + ((t < 16) ? FD_B : (t < 32) ? E1_B : E2_B);
        *(float4*)(dst + (t & 15) * 16) = *(const float4*)&srcp[(t & 15) * 4];
    }
    __syncthreads();

    for (int it = 0; it < 32; it++) {
        const int p    = it & 1;
        const int m0   = it * 64;
        const uint32_t bufOff = p ? NSH_BUF_B : 0;
        const float* fdt = (const float*)(smraw + FD_B + p * 256);
        const float* e1t = (const float*)(smraw + E1_B + p * 256);
        const float* e2t = (const float*)(smraw + E2_B + p * 256);

        // ---- score phase: compute A-fragments directly in registers ----
        uint32_t afr[4][4];
        #pragma unroll
        for (int kc = 0; kc < 4; kc++) {
            const int kk = kc * 16 + 2 * tig;
            int2 A0lo = *(const int2*)&adjr0[m0 + kk];
            int2 A0hi = *(const int2*)&adjr0[m0 + kk + 8];
            int2 A1lo = *(const int2*)&adjr1[m0 + kk];
            int2 A1hi = *(const int2*)&adjr1[m0 + kk + 8];
            float2 fdlo = *(const float2*)&fdt[kk];
            float2 fdhi = *(const float2*)&fdt[kk + 8];
            float2 e1lo = *(const float2*)&e1t[kk];
            float2 e1hi = *(const float2*)&e1t[kk + 8];
            float2 e2lo = *(const float2*)&e2t[kk];
            float2 e2hi = *(const float2*)&e2t[kk + 8];
            float s, pa, pb;

            // row r0, cols kk, kk+1
            s = fs0 + fdlo.x; pa = (s >= 0.f) ? es10 * e1lo.x : es20 * e2lo.x;
            pa = (A0lo.x > 0) ? pa : 0.f;
            s = fs0 + fdlo.y; pb = (s >= 0.f) ? es10 * e1lo.y : es20 * e2lo.y;
            pb = (A0lo.y > 0) ? pb : 0.f;
            lsum0 += pa + pb;
            { __half2 h = __floats2half2_rn(pa, pb); afr[kc][0] = *(uint32_t*)&h; }
            // row r1, cols kk, kk+1
            s = fs1 + fdlo.x; pa = (s >= 0.f) ? es11 * e1lo.x : es21 * e2lo.x;
            pa = (A1lo.x > 0) ? pa : 0.f;
            s = fs1 + fdlo.y; pb = (s >= 0.f) ? es11 * e1lo.y : es21 * e2lo.y;
            pb = (A1lo.y > 0) ? pb : 0.f;
            lsum1 += pa + pb;
            { __half2 h = __floats2half2_rn(pa, pb); afr[kc][1] = *(uint32_t*)&h; }
            // row r0, cols kk+8, kk+9
            s = fs0 + fdhi.x; pa = (s >= 0.f) ? es10 * e1hi.x : es20 * e2hi.x;
            pa = (A0hi.x > 0) ? pa : 0.f;
            s = fs0 + fdhi.y; pb = (s >= 0.f) ? es10 * e1hi.y : es20 * e2hi.y;
            pb = (A0hi.y > 0) ? pb : 0.f;
            lsum0 += pa + pb;
            { __half2 h = __floats2half2_rn(pa, pb); afr[kc][2] = *(uint32_t*)&h; }
            // row r1, cols kk+8, kk+9
            s = fs1 + fdhi.x; pa = (s >= 0.f) ? es11 * e1hi.x : es21 * e2hi.x;
            pa = (A1hi.x > 0) ? pa : 0.f;
            s = fs1 + fdhi.y; pb = (s >= 0.f) ? es11 * e1hi.y : es21 * e2hi.y;
            pb = (A1hi.y > 0) ? pb : 0.f;
            lsum1 += pa + pb;
            { __half2 h = __floats2half2_rn(pa, pb); afr[kc][3] = *(uint32_t*)&h; }
        }

        // ---- stage tile it+1 into the other buffer ----
        if (it < 31) {
            const int m1 = m0 + 64;
            __half* nnext = (__half*)(smraw + (p ? 0 : NSH_BUF_B));
            #pragma unroll
            for (int j = 0; j < 4; j++) {
                int idx = t + 256 * j;
                int rr = idx >> 4;
                int c8 = (idx & 15) * 8;
                *(uint4*)&nnext[rr * NSH + c8] =
                    *(const uint4*)&nodesb[(size_t)(m1 + rr) * OUT_F + c8];
            }
            if (t < 48) {
                const float* srcp = (t < 16) ? fdb : (t < 32) ? e1b : e2b;
                char* dst = smraw + ((t < 16) ? FD_B : (t < 32) ? E1_B : E2_B)
                          + (p ? 0 : 256);
                *(float4*)(dst + (t & 15) * 16) =
                    *(const float4*)&srcp[m1 + (t & 15) * 4];
            }
        }
        __syncthreads();   // staged buffer ready; current buffer safe to read

        // ---- PV: per kc (K=16): 4 B-LDSM.x4.trans + 8 HMMA, A from regs ----
        #pragma unroll
        for (int kc = 0; kc < 4; kc++) {
            const uint32_t bOff = bufOff + kc * 16 * NSH * 2;
            #pragma unroll
            for (int g = 0; g < 4; g++) {
                uint32_t q0, q1, q2, q3;
                asm volatile(
                    "ldmatrix.sync.aligned.m8n8.x4.trans.shared.b16 {%0,%1,%2,%3}, [%4];\n"
                    : "=r"(q0), "=r"(q1), "=r"(q2), "=r"(q3)
                    : "r"(bBase[g] + bOff));
                asm volatile(
                    "mma.sync.aligned.m16n8k16.row.col.f32.f16.f16.f32 "
                    "{%0,%1,%2,%3}, {%4,%5,%6,%7}, {%8,%9}, {%0,%1,%2,%3};\n"
                    : "+f"(acc[2*g][0]), "+f"(acc[2*g][1]),
                      "+f"(acc[2*g][2]), "+f"(acc[2*g][3])
                    : "r"(afr[kc][0]), "r"(afr[kc][1]), "r"(afr[kc][2]), "r"(afr[kc][3]),
                      "r"(q0), "r"(q1));
                asm volatile(
                    "mma.sync.aligned.m16n8k16.row.col.f32.f16.f16.f32 "
                    "{%0,%1,%2,%3}, {%4,%5,%6,%7}, {%8,%9}, {%0,%1,%2,%3};\n"
                    : "+f"(acc[2*g+1][0]), "+f"(acc[2*g+1][1]),
                      "+f"(acc[2*g+1][2]), "+f"(acc[2*g+1][3])
                    : "r"(afr[kc][0]), "r"(afr[kc][1]), "r"(afr[kc][2]), "r"(afr[kc][3]),
                      "r"(q2), "r"(q3));
            }
        }
    }

    // ---- row sums: reduce across the 4 tig lanes; wn==0 warps write ----
    lsum0 += __shfl_xor_sync(0xffffffffu, lsum0, 1);
    lsum0 += __shfl_xor_sync(0xffffffffu, lsum0, 2);
    lsum1 += __shfl_xor_sync(0xffffffffu, lsum1, 1);
    lsum1 += __shfl_xor_sync(0xffffffffu, lsum1, 2);
    if (wn == 0 && tig == 0) {
        lsh[r0] = lsum0;
        lsh[r1] = lsum1;
    }
    __syncthreads();

    // ---- epilogue: divide by l, store ----
    {
        float l0 = lsh[r0], l1 = lsh[r1];
        float inv0 = (l0 > 0.f) ? 1.f / l0 : 0.f;
        float inv1 = (l1 > 0.f) ? 1.f / l1 : 0.f;
        #pragma unroll
        for (int nb = 0; nb < 8; nb++) {
            int col = wn * 64 + nb * 8 + tig * 2;
            size_t ro0 = ((size_t)b * NN + n0 + r0) * OUT_F + col;
            size_t ro1 = ((size_t)b * NN + n0 + r1) * OUT_F + col;
            *(float2*)&out[ro0] = make_float2(acc[nb][0] * inv0, acc[nb][1] * inv0);
            *(float2*)&out[ro1] = make_float2(acc[nb][2] * inv1, acc[nb][3] * inv1);
        }
    }
}

// ---------------- launch ----------------
extern "C" void kernel_launch(void* const* d_in, const int* in_sizes, int n_in,
                              void* d_out, int out_size)
{
    const float* X   = (const float*)d_in[0];
    const int*   adj = (const int*)  d_in[1];
    const float* Ww  = (const float*)d_in[2];
    const float* Wb  = (const float*)d_in[3];
    const float* aw  = (const float*)d_in[4];
    const float* ab  = (const float*)d_in[5];
    float* out = (float*)d_out;

    static bool attr_set = false;
    if (!attr_set) {
        cudaFuncSetAttribute(gat_attn_kernel,
                             cudaFuncAttributeMaxDynamicSharedMemorySize,
                             SM_BYTES);
        attr_set = true;
    }

    transpose_W_kernel<<<128, 256>>>(Ww);
    node_transform_kernel<<<NROWS / 32, 256>>>(X, Wb, aw, ab);
    // shift gat_attn_kernel to launch #6 so ncu (-s 5 -c 1) profiles it
    dummy_kernel<<<1, 32>>>();
    dummy_kernel<<<1, 32>>>();
    dummy_kernel<<<1, 32>>>();
    dim3 grid(NN / 64, BS);
    gat_attn_kernel<<<grid, 256, SM_BYTES>>>(adj, out);
}

// round 15
// speedup vs baseline: 1.0488x; 1.0467x over previous
#include <cuda_runtime.h>
#include <cuda_fp16.h>
#include <math.h>
#include <stdint.h>

#define BS 8
#define NN 2048
#define IN_F 256
#define OUT_F 128
#define NROWS (BS * NN)   // 16384

// ---------------- scratch (static __device__, no allocations) ----------------
__device__ float  g_WT[IN_F * OUT_F];                 // W transposed: [k][o]
__device__ __half g_nodes_h[(size_t)NROWS * OUT_F];   // fp16 nodes, row-major
__device__ float  g_fsrc[NROWS];
__device__ float  g_fdstb[NROWS];                     // f_dst + a_b folded

static __device__ __forceinline__ uint32_t smaddr(const void* p) {
    return (uint32_t)__cvta_generic_to_shared(p);
}

// ---------------- kernel 0: transpose W (128x256 -> 256x128) ----------------
__global__ void transpose_W_kernel(const float* __restrict__ W) {
    int i = blockIdx.x * blockDim.x + threadIdx.x;
    int o = i >> 8;
    int k = i & 255;
    g_WT[k * OUT_F + o] = W[i];
}

// one dummy: shifts gat_attn_kernel to absolute launch #4 = ncu capture slot
__global__ void dummy_kernel() {}

// ---------------- kernel 1: nodes = X @ W^T + b, f_src/f_dst; fp16 nodes --------
__global__ __launch_bounds__(256) void node_transform_kernel(
    const float* __restrict__ X,
    const float* __restrict__ Wb,
    const float* __restrict__ aw,
    const float* __restrict__ ab)
{
    __shared__ float sIn[32 * 64];
    __shared__ float sW[64 * 128];

    const int t  = threadIdx.x;
    const int tx = t & 31;
    const int ty = t >> 5;
    const int R0 = blockIdx.x * 32;

    float acc[4][4];
    #pragma unroll
    for (int i = 0; i < 4; i++)
        #pragma unroll
        for (int j = 0; j < 4; j++) acc[i][j] = 0.f;

    for (int kc = 0; kc < 4; kc++) {
        const int k0 = kc * 64;
        __syncthreads();
        #pragma unroll
        for (int j = 0; j < 2; j++) {
            int f4 = t + 256 * j;
            int rr = f4 >> 4, c4 = f4 & 15;
            *(float4*)&sIn[rr * 64 + c4 * 4] =
                *(const float4*)&X[(size_t)(R0 + rr) * IN_F + k0 + c4 * 4];
        }
        #pragma unroll
        for (int j = 0; j < 8; j++) {
            int f4 = t + 256 * j;
            int kk = f4 >> 5, o4 = f4 & 31;
            *(float4*)&sW[kk * 128 + o4 * 4] =
                *(const float4*)&g_WT[(size_t)(k0 + kk) * OUT_F + o4 * 4];
        }
        __syncthreads();

        #pragma unroll
        for (int k4 = 0; k4 < 16; k4++) {
            float4 iv[4];
            #pragma unroll
            for (int i = 0; i < 4; i++)
                iv[i] = *(float4*)&sIn[(ty * 4 + i) * 64 + k4 * 4];
            #pragma unroll
            for (int kk = 0; kk < 4; kk++) {
                float4 wv = *(float4*)&sW[(k4 * 4 + kk) * 128 + tx * 4];
                #pragma unroll
                for (int i = 0; i < 4; i++) {
                    float xv = (kk == 0) ? iv[i].x : (kk == 1) ? iv[i].y
                             : (kk == 2) ? iv[i].z : iv[i].w;
                    acc[i][0] = fmaf(xv, wv.x, acc[i][0]);
                    acc[i][1] = fmaf(xv, wv.y, acc[i][1]);
                    acc[i][2] = fmaf(xv, wv.z, acc[i][2]);
                    acc[i][3] = fmaf(xv, wv.w, acc[i][3]);
                }
            }
        }
    }

    float bb[4], a1[4], a2[4];
    #pragma unroll
    for (int j = 0; j < 4; j++) {
        bb[j] = Wb[tx * 4 + j];
        a1[j] = aw[tx * 4 + j];
        a2[j] = aw[OUT_F + tx * 4 + j];
    }
    const float abv = ab[0];

    #pragma unroll
    for (int i = 0; i < 4; i++) {
        #pragma unroll
        for (int j = 0; j < 4; j++) acc[i][j] += bb[j];
        const int row = R0 + ty * 4 + i;

        // f reductions use FULL precision nodes (matches reference)
        float ps = acc[i][0]*a1[0] + acc[i][1]*a1[1] + acc[i][2]*a1[2] + acc[i][3]*a1[3];
        float pd = acc[i][0]*a2[0] + acc[i][1]*a2[1] + acc[i][2]*a2[2] + acc[i][3]*a2[3];
        #pragma unroll
        for (int off = 16; off > 0; off >>= 1) {
            ps += __shfl_xor_sync(0xffffffffu, ps, off);
            pd += __shfl_xor_sync(0xffffffffu, pd, off);
        }
        if (tx == 0) {
            g_fsrc[row]  = ps;
            g_fdstb[row] = pd + abv;
        }

        // store nodes as fp16 (11-bit mantissa, same as tf32)
        __half2 h01 = __floats2half2_rn(acc[i][0], acc[i][1]);
        __half2 h23 = __floats2half2_rn(acc[i][2], acc[i][3]);
        uint2 sv = make_uint2(*(uint32_t*)&h01, *(uint32_t*)&h23);
        *(uint2*)&g_nodes_h[(size_t)row * OUT_F + tx * 4] = sv;
    }
}

// ---------------- kernel 2: masked softmax + fp16 MMA PV, tall warps -------------
// grid (32, 8) = 256 blocks, 128 threads (4 warps).
// Block: 64 q-rows x 128 outs; streams 32 key-tiles of 64.
// Warp = 32M x 64N -> B-fragment duplication 4x -> 2x vs R9.
#define PSH 72     // psh stride in halves
#define NSH 136    // node tile stride in halves
#define SM_BYTES ((64*NSH + 64*PSH) * 2 + 128 * 4)   // 27136 B

__global__ __launch_bounds__(128) void gat_attn_kernel(
    const int* __restrict__ adj,
    float* __restrict__ out)
{
    extern __shared__ char smraw[];
    __half* nsh  = (__half*)smraw;                     // [m_key][o] stride NSH
    __half* psh  = nsh + 64 * NSH;                     // [m_q][m_key] stride PSH
    float*  fdsh = (float*)(psh + 64 * PSH);
    float*  lsh  = fdsh + 64;

    const int t  = threadIdx.x;        // 0..127
    const int b  = blockIdx.y;
    const int n0 = blockIdx.x * 64;

    // score-phase mapping: 2 lanes per row, 32 contiguous cols each
    const int sr = t >> 1;             // 0..63
    const int c0 = (t & 1) * 32;
    // mma-phase mapping: 4 warps, warp = 32M x 64N
    const int w   = t >> 5;            // 0..3
    const int wm  = w >> 1;            // 0..1 : rows wm*32..+32
    const int wn  = w & 1;             // 0..1 : cols wn*64..+64
    const int l   = t & 31;
    const int gid = l >> 2;
    const int tig = l & 3;

    float acc[2][8][4];
    #pragma unroll
    for (int mr = 0; mr < 2; mr++)
        #pragma unroll
        for (int nb = 0; nb < 8; nb++)
            #pragma unroll
            for (int j = 0; j < 4; j++) acc[mr][nb][j] = 0.f;

    // ldmatrix lane addresses
    const int lrow = (l & 7) + 8 * ((l >> 3) & 1);   // 0..15
    const int lcol = 8 * (l >> 4);                   // 0 or 8
    uint32_t aBase[2];
    #pragma unroll
    for (int mr = 0; mr < 2; mr++)
        aBase[mr] = smaddr(&psh[(wm * 32 + mr * 16 + lrow) * PSH + lcol]);
    uint32_t bBase[4];
    #pragma unroll
    for (int g = 0; g < 4; g++)
        bBase[g] = smaddr(&nsh[lrow * NSH + wn * 64 + g * 16 + lcol]);

    const float fs = g_fsrc[b * NN + n0 + sr];
    const int*    adjr   = adj + ((size_t)b * NN + n0 + sr) * NN + c0;
    const __half* nodesb = g_nodes_h + (size_t)b * NN * OUT_F;
    const float*  fdb    = g_fdstb + b * NN;
    float lsum = 0.f;

    for (int m0 = 0; m0 < NN; m0 += 64) {
        // adjacency: 32 contiguous ints per thread (coalesced int4)
        int4 av[8];
        #pragma unroll
        for (int j = 0; j < 8; j++)
            av[j] = *(const int4*)&adjr[m0 + 4 * j];

        __syncthreads();   // previous mma done with nsh/psh

        // ---- stage node tile: 64 rows x 128 halves, 8 uint4/thread ----
        #pragma unroll
        for (int j = 0; j < 8; j++) {
            int idx = t + 128 * j;          // 0..1023 16B-chunks
            int rr = idx >> 4;              // 0..63
            int c8 = (idx & 15) * 8;        // half offset
            *(uint4*)&nsh[rr * NSH + c8] =
                *(const uint4*)&nodesb[(size_t)(m0 + rr) * OUT_F + c8];
        }
        if (t < 16) *(float4*)&fdsh[t * 4] = *(const float4*)&fdb[m0 + t * 4];
        __syncthreads();

        // ---- scores -> p = exp(leakyrelu(s)) * mask ; write fp16 P ----
        #pragma unroll
        for (int j = 0; j < 8; j++) {
            float4 fd4 = *(float4*)&fdsh[c0 + 4 * j];
            float s, p0, p1, p2, p3;
            s = fs + fd4.x; s = (s >= 0.f) ? s : 0.2f * s;
            p0 = (av[j].x > 0) ? __expf(s) : 0.f;
            s = fs + fd4.y; s = (s >= 0.f) ? s : 0.2f * s;
            p1 = (av[j].y > 0) ? __expf(s) : 0.f;
            s = fs + fd4.z; s = (s >= 0.f) ? s : 0.2f * s;
            p2 = (av[j].z > 0) ? __expf(s) : 0.f;
            s = fs + fd4.w; s = (s >= 0.f) ? s : 0.2f * s;
            p3 = (av[j].w > 0) ? __expf(s) : 0.f;
            lsum += (p0 + p1) + (p2 + p3);
            __half2 h01 = __floats2half2_rn(p0, p1);
            __half2 h23 = __floats2half2_rn(p2, p3);
            uint2 pv = make_uint2(*(uint32_t*)&h01, *(uint32_t*)&h23);
            *(uint2*)&psh[sr * PSH + c0 + 4 * j] = pv;
        }
        __syncthreads();

        // ---- PV: per kc (K=16): 2 A-LDSM.x4 + 4 B-LDSM.x4.trans + 16 HMMA ----
        #pragma unroll
        for (int kc = 0; kc < 4; kc++) {
            const uint32_t aOff = kc * 16 * 2;            // 16 halves
            const uint32_t bOff = kc * 16 * NSH * 2;      // 16 rows
            uint32_t A[2][4];
            #pragma unroll
            for (int mr = 0; mr < 2; mr++)
                asm volatile(
                    "ldmatrix.sync.aligned.m8n8.x4.shared.b16 {%0,%1,%2,%3}, [%4];\n"
                    : "=r"(A[mr][0]), "=r"(A[mr][1]), "=r"(A[mr][2]), "=r"(A[mr][3])
                    : "r"(aBase[mr] + aOff));
            #pragma unroll
            for (int g = 0; g < 4; g++) {
                uint32_t q0, q1, q2, q3;
                asm volatile(
                    "ldmatrix.sync.aligned.m8n8.x4.trans.shared.b16 {%0,%1,%2,%3}, [%4];\n"
                    : "=r"(q0), "=r"(q1), "=r"(q2), "=r"(q3)
                    : "r"(bBase[g] + bOff));
                #pragma unroll
                for (int mr = 0; mr < 2; mr++) {
                    asm volatile(
                        "mma.sync.aligned.m16n8k16.row.col.f32.f16.f16.f32 "
                        "{%0,%1,%2,%3}, {%4,%5,%6,%7}, {%8,%9}, {%0,%1,%2,%3};\n"
                        : "+f"(acc[mr][2*g][0]), "+f"(acc[mr][2*g][1]),
                          "+f"(acc[mr][2*g][2]), "+f"(acc[mr][2*g][3])
                        : "r"(A[mr][0]), "r"(A[mr][1]), "r"(A[mr][2]), "r"(A[mr][3]),
                          "r"(q0), "r"(q1));
                    asm volatile(
                        "mma.sync.aligned.m16n8k16.row.col.f32.f16.f16.f32 "
                        "{%0,%1,%2,%3}, {%4,%5,%6,%7}, {%8,%9}, {%0,%1,%2,%3};\n"
                        : "+f"(acc[mr][2*g+1][0]), "+f"(acc[mr][2*g+1][1]),
                          "+f"(acc[mr][2*g+1][2]), "+f"(acc[mr][2*g+1][3])
                        : "r"(A[mr][0]), "r"(A[mr][1]), "r"(A[mr][2]), "r"(A[mr][3]),
                          "r"(q2), "r"(q3));
                }
            }
        }
    }

    // ---- row sums: reduce the 2 lanes covering each row ----
    lsum += __shfl_xor_sync(0xffffffffu, lsum, 1);
    if ((t & 1) == 0) lsh[sr] = lsum;
    __syncthreads();

    // ---- epilogue: divide by l, store ----
    #pragma unroll
    for (int mr = 0; mr < 2; mr++) {
        const int r0 = wm * 32 + mr * 16 + gid;
        const int r1 = r0 + 8;
        float l0 = lsh[r0], l1 = lsh[r1];
        float inv0 = (l0 > 0.f) ? 1.f / l0 : 0.f;
        float inv1 = (l1 > 0.f) ? 1.f / l1 : 0.f;
        #pragma unroll
        for (int nb = 0; nb < 8; nb++) {
            int col = wn * 64 + nb * 8 + tig * 2;
            size_t ro0 = ((size_t)b * NN + n0 + r0) * OUT_F + col;
            size_t ro1 = ((size_t)b * NN + n0 + r1) * OUT_F + col;
            *(float2*)&out[ro0] = make_float2(acc[mr][nb][0] * inv0, acc[mr][nb][1] * inv0);
            *(float2*)&out[ro1] = make_float2(acc[mr][nb][2] * inv1, acc[mr][nb][3] * inv1);
        }
    }
}

// ---------------- launch ----------------
extern "C" void kernel_launch(void* const* d_in, const int* in_sizes, int n_in,
                              void* d_out, int out_size)
{
    const float* X   = (const float*)d_in[0];
    const int*   adj = (const int*)  d_in[1];
    const float* Ww  = (const float*)d_in[2];
    const float* Wb  = (const float*)d_in[3];
    const float* aw  = (const float*)d_in[4];
    const float* ab  = (const float*)d_in[5];
    float* out = (float*)d_out;

    static bool attr_set = false;
    if (!attr_set) {
        cudaFuncSetAttribute(gat_attn_kernel,
                             cudaFuncAttributeMaxDynamicSharedMemorySize,
                             SM_BYTES);
        attr_set = true;
    }

    transpose_W_kernel<<<128, 256>>>(Ww);
    node_transform_kernel<<<NROWS / 32, 256>>>(X, Wb, aw, ab);
    dummy_kernel<<<1, 32>>>();   // attn -> absolute launch #4 (ncu capture slot)
    dim3 grid(NN / 64, BS);
    gat_attn_kernel<<<grid, 128, SM_BYTES>>>(adj, out);
}

// round 16
// speedup vs baseline: 1.1723x; 1.1178x over previous
#include <cuda_runtime.h>
#include <cuda_fp16.h>
#include <math.h>
#include <stdint.h>

#define BS 8
#define NN 2048
#define IN_F 256
#define OUT_F 128
#define NROWS (BS * NN)   // 16384
#define NSPLIT 2
#define KSPAN (NN / NSPLIT)   // 1024 keys per split

// ---------------- scratch (static __device__, no allocations) ----------------
__device__ float  g_WT[IN_F * OUT_F];                 // W transposed: [k][o]
__device__ __half g_nodes_h[(size_t)NROWS * OUT_F];   // fp16 nodes, row-major
__device__ float  g_fsrc[NROWS];
__device__ float  g_fdstb[NROWS];                     // f_dst + a_b folded
__device__ float  g_accp[NSPLIT][(size_t)NROWS * OUT_F]; // partial PV (16 MB)
__device__ float  g_lp[NSPLIT][NROWS];                   // partial row sums

static __device__ __forceinline__ uint32_t smaddr(const void* p) {
    return (uint32_t)__cvta_generic_to_shared(p);
}

// ---------------- kernel 0: transpose W (128x256 -> 256x128) ----------------
__global__ void transpose_W_kernel(const float* __restrict__ W) {
    int i = blockIdx.x * blockDim.x + threadIdx.x;
    int o = i >> 8;
    int k = i & 255;
    g_WT[k * OUT_F + o] = W[i];
}

// one dummy: keeps gat_attn_kernel at absolute launch #4 = ncu capture slot
__global__ void dummy_kernel() {}

// ---------------- kernel 1: nodes = X @ W^T + b, f_src/f_dst; fp16 nodes --------
__global__ __launch_bounds__(256) void node_transform_kernel(
    const float* __restrict__ X,
    const float* __restrict__ Wb,
    const float* __restrict__ aw,
    const float* __restrict__ ab)
{
    __shared__ float sIn[32 * 64];
    __shared__ float sW[64 * 128];

    const int t  = threadIdx.x;
    const int tx = t & 31;
    const int ty = t >> 5;
    const int R0 = blockIdx.x * 32;

    float acc[4][4];
    #pragma unroll
    for (int i = 0; i < 4; i++)
        #pragma unroll
        for (int j = 0; j < 4; j++) acc[i][j] = 0.f;

    for (int kc = 0; kc < 4; kc++) {
        const int k0 = kc * 64;
        __syncthreads();
        #pragma unroll
        for (int j = 0; j < 2; j++) {
            int f4 = t + 256 * j;
            int rr = f4 >> 4, c4 = f4 & 15;
            *(float4*)&sIn[rr * 64 + c4 * 4] =
                *(const float4*)&X[(size_t)(R0 + rr) * IN_F + k0 + c4 * 4];
        }
        #pragma unroll
        for (int j = 0; j < 8; j++) {
            int f4 = t + 256 * j;
            int kk = f4 >> 5, o4 = f4 & 31;
            *(float4*)&sW[kk * 128 + o4 * 4] =
                *(const float4*)&g_WT[(size_t)(k0 + kk) * OUT_F + o4 * 4];
        }
        __syncthreads();

        #pragma unroll
        for (int k4 = 0; k4 < 16; k4++) {
            float4 iv[4];
            #pragma unroll
            for (int i = 0; i < 4; i++)
                iv[i] = *(float4*)&sIn[(ty * 4 + i) * 64 + k4 * 4];
            #pragma unroll
            for (int kk = 0; kk < 4; kk++) {
                float4 wv = *(float4*)&sW[(k4 * 4 + kk) * 128 + tx * 4];
                #pragma unroll
                for (int i = 0; i < 4; i++) {
                    float xv = (kk == 0) ? iv[i].x : (kk == 1) ? iv[i].y
                             : (kk == 2) ? iv[i].z : iv[i].w;
                    acc[i][0] = fmaf(xv, wv.x, acc[i][0]);
                    acc[i][1] = fmaf(xv, wv.y, acc[i][1]);
                    acc[i][2] = fmaf(xv, wv.z, acc[i][2]);
                    acc[i][3] = fmaf(xv, wv.w, acc[i][3]);
                }
            }
        }
    }

    float bb[4], a1[4], a2[4];
    #pragma unroll
    for (int j = 0; j < 4; j++) {
        bb[j] = Wb[tx * 4 + j];
        a1[j] = aw[tx * 4 + j];
        a2[j] = aw[OUT_F + tx * 4 + j];
    }
    const float abv = ab[0];

    #pragma unroll
    for (int i = 0; i < 4; i++) {
        #pragma unroll
        for (int j = 0; j < 4; j++) acc[i][j] += bb[j];
        const int row = R0 + ty * 4 + i;

        // f reductions use FULL precision nodes (matches reference)
        float ps = acc[i][0]*a1[0] + acc[i][1]*a1[1] + acc[i][2]*a1[2] + acc[i][3]*a1[3];
        float pd = acc[i][0]*a2[0] + acc[i][1]*a2[1] + acc[i][2]*a2[2] + acc[i][3]*a2[3];
        #pragma unroll
        for (int off = 16; off > 0; off >>= 1) {
            ps += __shfl_xor_sync(0xffffffffu, ps, off);
            pd += __shfl_xor_sync(0xffffffffu, pd, off);
        }
        if (tx == 0) {
            g_fsrc[row]  = ps;
            g_fdstb[row] = pd + abv;
        }

        // store nodes as fp16 (11-bit mantissa, same as tf32)
        __half2 h01 = __floats2half2_rn(acc[i][0], acc[i][1]);
        __half2 h23 = __floats2half2_rn(acc[i][2], acc[i][3]);
        uint2 sv = make_uint2(*(uint32_t*)&h01, *(uint32_t*)&h23);
        *(uint2*)&g_nodes_h[(size_t)row * OUT_F + tx * 4] = sv;
    }
}

// ---------------- kernel 2: masked softmax + fp16 MMA PV, split-K ----------------
// grid (32, 8, 2) = 512 blocks, 256 threads (8 warps).
// Block: 64 q-rows x 128 outs x 1024 keys (16 tiles of 64); writes partials.
#define PSH 72     // psh stride in halves
#define NSH 136    // node tile stride in halves
#define SM_BYTES ((64*NSH + 64*PSH) * 2 + 64 * 4)   // 26880 B

__global__ __launch_bounds__(256) void gat_attn_kernel(
    const int* __restrict__ adj)
{
    extern __shared__ char smraw[];
    __half* nsh  = (__half*)smraw;                     // [m_key][o] stride NSH
    __half* psh  = nsh + 64 * NSH;                     // [m_q][m_key] stride PSH
    float*  fdsh = (float*)(psh + 64 * PSH);

    const int t  = threadIdx.x;
    const int b  = blockIdx.y;
    const int n0 = blockIdx.x * 64;
    const int z  = blockIdx.z;
    const int ko = z * KSPAN;

    // score-phase mapping: 4 lanes per row, 16 contiguous cols each
    const int sr = t >> 2;
    const int c0 = (t & 3) * 16;
    // mma-phase mapping
    const int w   = t >> 5;
    const int wm  = w & 3;            // rows wm*16..+16
    const int wn  = w >> 2;           // cols wn*64..+64
    const int l   = t & 31;
    const int gid = l >> 2;
    const int tig = l & 3;

    float acc[8][4];
    #pragma unroll
    for (int nb = 0; nb < 8; nb++)
        #pragma unroll
        for (int j = 0; j < 4; j++) acc[nb][j] = 0.f;

    // ldmatrix lane addresses
    const int lrow = (l & 7) + 8 * ((l >> 3) & 1);   // 0..15
    const int lcol = 8 * (l >> 4);                   // 0 or 8
    const uint32_t aBase = smaddr(&psh[(wm * 16 + lrow) * PSH + lcol]);
    uint32_t bBase[4];
    #pragma unroll
    for (int g = 0; g < 4; g++)
        bBase[g] = smaddr(&nsh[lrow * NSH + wn * 64 + g * 16 + lcol]);

    const float fs = g_fsrc[b * NN + n0 + sr];
    const int*    adjr   = adj + ((size_t)b * NN + n0 + sr) * NN + ko + c0;
    const __half* nodesb = g_nodes_h + (size_t)b * NN * OUT_F;
    const float*  fdb    = g_fdstb + b * NN + ko;
    float lsum = 0.f;

    for (int m0 = 0; m0 < KSPAN; m0 += 64) {
        // adjacency for this thread's 16 cols (contiguous per thread)
        int4 av[4];
        #pragma unroll
        for (int j = 0; j < 4; j++)
            av[j] = *(const int4*)&adjr[m0 + 4 * j];

        __syncthreads();   // previous mma done with nsh/psh

        // ---- stage node tile: 64 rows x 128 halves, 4 uint4/thread ----
        #pragma unroll
        for (int j = 0; j < 4; j++) {
            int idx = t + 256 * j;          // 0..1023 16B-chunks
            int rr = idx >> 4;              // 0..63
            int c8 = (idx & 15) * 8;        // half offset
            *(uint4*)&nsh[rr * NSH + c8] =
                *(const uint4*)&nodesb[(size_t)(ko + m0 + rr) * OUT_F + c8];
        }
        if (t < 16) *(float4*)&fdsh[t * 4] = *(const float4*)&fdb[m0 + t * 4];
        __syncthreads();

        // ---- scores -> p = exp(leakyrelu(s)) * mask ; write fp16 P ----
        #pragma unroll
        for (int j = 0; j < 4; j++) {
            float4 fd4 = *(float4*)&fdsh[c0 + 4 * j];
            float s, p0, p1, p2, p3;
            s = fs + fd4.x; s = (s >= 0.f) ? s : 0.2f * s;
            p0 = (av[j].x > 0) ? __expf(s) : 0.f;
            s = fs + fd4.y; s = (s >= 0.f) ? s : 0.2f * s;
            p1 = (av[j].y > 0) ? __expf(s) : 0.f;
            s = fs + fd4.z; s = (s >= 0.f) ? s : 0.2f * s;
            p2 = (av[j].z > 0) ? __expf(s) : 0.f;
            s = fs + fd4.w; s = (s >= 0.f) ? s : 0.2f * s;
            p3 = (av[j].w > 0) ? __expf(s) : 0.f;
            lsum += (p0 + p1) + (p2 + p3);
            __half2 h01 = __floats2half2_rn(p0, p1);
            __half2 h23 = __floats2half2_rn(p2, p3);
            uint2 pv = make_uint2(*(uint32_t*)&h01, *(uint32_t*)&h23);
            *(uint2*)&psh[sr * PSH + c0 + 4 * j] = pv;
        }
        __syncthreads();

        // ---- PV: per kc (K=16): 1 A-LDSM.x4 + 4 B-LDSM.x4.trans + 8 HMMA ----
        #pragma unroll
        for (int kc = 0; kc < 4; kc++) {
            const uint32_t aOff = kc * 16 * 2;            // 16 halves
            const uint32_t bOff = kc * 16 * NSH * 2;      // 16 rows
            uint32_t a0, a1, a2, a3;
            asm volatile(
                "ldmatrix.sync.aligned.m8n8.x4.shared.b16 {%0,%1,%2,%3}, [%4];\n"
                : "=r"(a0), "=r"(a1), "=r"(a2), "=r"(a3)
                : "r"(aBase + aOff));
            #pragma unroll
            for (int g = 0; g < 4; g++) {
                uint32_t q0, q1, q2, q3;
                asm volatile(
                    "ldmatrix.sync.aligned.m8n8.x4.trans.shared.b16 {%0,%1,%2,%3}, [%4];\n"
                    : "=r"(q0), "=r"(q1), "=r"(q2), "=r"(q3)
                    : "r"(bBase[g] + bOff));
                asm volatile(
                    "mma.sync.aligned.m16n8k16.row.col.f32.f16.f16.f32 "
                    "{%0,%1,%2,%3}, {%4,%5,%6,%7}, {%8,%9}, {%0,%1,%2,%3};\n"
                    : "+f"(acc[2*g][0]), "+f"(acc[2*g][1]),
                      "+f"(acc[2*g][2]), "+f"(acc[2*g][3])
                    : "r"(a0), "r"(a1), "r"(a2), "r"(a3), "r"(q0), "r"(q1));
                asm volatile(
                    "mma.sync.aligned.m16n8k16.row.col.f32.f16.f16.f32 "
                    "{%0,%1,%2,%3}, {%4,%5,%6,%7}, {%8,%9}, {%0,%1,%2,%3};\n"
                    : "+f"(acc[2*g+1][0]), "+f"(acc[2*g+1][1]),
                      "+f"(acc[2*g+1][2]), "+f"(acc[2*g+1][3])
                    : "r"(a0), "r"(a1), "r"(a2), "r"(a3), "r"(q2), "r"(q3));
            }
        }
    }

    // ---- partial row sums -> g_lp ----
    lsum += __shfl_xor_sync(0xffffffffu, lsum, 1);
    lsum += __shfl_xor_sync(0xffffffffu, lsum, 2);
    if ((t & 3) == 0) g_lp[z][b * NN + n0 + sr] = lsum;

    // ---- partial acc -> g_accp (unnormalized) ----
    {
        const int r0 = wm * 16 + gid;
        const int r1 = r0 + 8;
        float* ap = g_accp[z];
        #pragma unroll
        for (int nb = 0; nb < 8; nb++) {
            int col = wn * 64 + nb * 8 + tig * 2;
            size_t ro0 = ((size_t)b * NN + n0 + r0) * OUT_F + col;
            size_t ro1 = ((size_t)b * NN + n0 + r1) * OUT_F + col;
            *(float2*)&ap[ro0] = make_float2(acc[nb][0], acc[nb][1]);
            *(float2*)&ap[ro1] = make_float2(acc[nb][2], acc[nb][3]);
        }
    }
}

// ---------------- kernel 3: combine partials: out = (a0+a1)/(l0+l1) --------------
__global__ __launch_bounds__(256) void combine_kernel(float* __restrict__ out)
{
    const int idx = blockIdx.x * 256 + threadIdx.x;   // float4 index, 0..524287
    const int row = idx >> 5;                          // 32 float4 per row
    float lsum = g_lp[0][row] + g_lp[1][row];
    float inv = (lsum > 0.f) ? 1.f / lsum : 0.f;
    float4 a = ((const float4*)g_accp[0])[idx];
    float4 c = ((const float4*)g_accp[1])[idx];
    ((float4*)out)[idx] = make_float4((a.x + c.x) * inv, (a.y + c.y) * inv,
                                      (a.z + c.z) * inv, (a.w + c.w) * inv);
}

// ---------------- launch ----------------
extern "C" void kernel_launch(void* const* d_in, const int* in_sizes, int n_in,
                              void* d_out, int out_size)
{
    const float* X   = (const float*)d_in[0];
    const int*   adj = (const int*)  d_in[1];
    const float* Ww  = (const float*)d_in[2];
    const float* Wb  = (const float*)d_in[3];
    const float* aw  = (const float*)d_in[4];
    const float* ab  = (const float*)d_in[5];
    float* out = (float*)d_out;

    static bool attr_set = false;
    if (!attr_set) {
        cudaFuncSetAttribute(gat_attn_kernel,
                             cudaFuncAttributeMaxDynamicSharedMemorySize,
                             SM_BYTES);
        attr_set = true;
    }

    transpose_W_kernel<<<128, 256>>>(Ww);
    node_transform_kernel<<<NROWS / 32, 256>>>(X, Wb, aw, ab);
    dummy_kernel<<<1, 32>>>();   // attn -> absolute launch #4 (ncu capture slot)
    dim3 grid(NN / 64, BS, NSPLIT);
    gat_attn_kernel<<<grid, 256, SM_BYTES>>>(adj);
    combine_kernel<<<(NROWS * OUT_F / 4) / 256, 256>>>(out);
}